// round 13
// baseline (speedup 1.0000x reference)
#include <cuda_runtime.h>
#include <math.h>

#define N_OBS   256
#define N_Y     128
#define N_X     64
#define NITERS  150
#define NTHREADS 512
#define NWARPS   16
#define ROWS_PER_WARP 16

__device__ float g_ep[N_OBS * N_Y];             // ep row-major [t][j]
__device__ float g_yhat_fallback[N_OBS * N_Y];

// ---- packed f32x2 helpers (sm_103a) ---------------------------------------
typedef unsigned long long u64;
__device__ __forceinline__ void fma2(u64& d, u64 a, u64 b) {
    asm("fma.rn.f32x2 %0, %1, %2, %0;" : "+l"(d) : "l"(a), "l"(b));
}
__device__ __forceinline__ void add2(u64& d, u64 a) {
    asm("add.rn.f32x2 %0, %0, %1;" : "+l"(d) : "l"(a));
}
__device__ __forceinline__ u64 pk2(float lo, float hi) {
    u64 r;
    asm("mov.b64 %0, {%1, %2};" : "=l"(r) : "f"(lo), "f"(hi));
    return r;
}
__device__ __forceinline__ float upk_lo(u64 v) {
    float lo, hi; asm("mov.b64 {%0, %1}, %2;" : "=f"(lo), "=f"(hi) : "l"(v)); return lo;
}
__device__ __forceinline__ float upk_hi(u64 v) {
    float lo, hi; asm("mov.b64 {%0, %1}, %2;" : "=f"(lo), "=f"(hi) : "l"(v)); return hi;
}
__device__ __forceinline__ float upk_sum(u64 v) {
    float lo, hi; asm("mov.b64 {%0, %1}, %2;" : "=f"(lo), "=f"(hi) : "l"(v)); return lo + hi;
}

// ---------------------------------------------------------------------------
// Kernel 1: Y_hat = X @ W^T + b ; ep = Y - Y_hat (row-major)
// ---------------------------------------------------------------------------
__global__ void prep_kernel(const float* __restrict__ X,
                            const float* __restrict__ Y,
                            const float* __restrict__ W,
                            const float* __restrict__ b,
                            float* __restrict__ yhat_out) {
    __shared__ float Xs[N_X];
    __shared__ float Ws[N_Y * (N_X + 1)];
    const int t = blockIdx.x;
    const int i = threadIdx.x;

    if (i < N_X) Xs[i] = X[t * N_X + i];
    for (int idx = i; idx < N_Y * N_X; idx += blockDim.x) {
        int r = idx >> 6, cx = idx & 63;
        Ws[r * (N_X + 1) + cx] = W[idx];
    }
    __syncthreads();

    float acc = b[i];
#pragma unroll
    for (int x = 0; x < N_X; x++) acc += Xs[x] * Ws[i * (N_X + 1) + x];

    yhat_out[t * N_Y + i] = acc;
    g_ep[t * N_Y + i] = Y[t * N_Y + i] - acc;
}

// ---------------------------------------------------------------------------
// Block-layout warp-local simplex projection: sums 16 per-warp partials,
// v = z - lr*(g - gamma*yh), z = proj_simplex(v). i = lane*4 + r.
// ---------------------------------------------------------------------------
__device__ __forceinline__ void cswap(float& a, float& b, bool asc) {
    const float lo = fminf(a, b), hi = fmaxf(a, b);
    a = asc ? lo : hi;
    b = asc ? hi : lo;
}

__device__ __forceinline__ void project_warp16(const float* __restrict__ part,
                                               const float* __restrict__ yh,
                                               float* __restrict__ zz,
                                               float lr, float gamma) {
    const unsigned FULL = 0xffffffffu;
    const int lane = threadIdx.x & 31;

    float g0 = 0.0f, g1 = 0.0f, g2 = 0.0f, g3 = 0.0f;
#pragma unroll
    for (int w = 0; w < NWARPS; w++) {
        const float4 p = *reinterpret_cast<const float4*>(&part[w * N_Y + lane * 4]);
        g0 += p.x; g1 += p.y; g2 += p.z; g3 += p.w;
    }
    const float4 yv = *reinterpret_cast<const float4*>(&yh[lane * 4]);
    const float4 zv = *reinterpret_cast<const float4*>(&zz[lane * 4]);

    float vorig[4], val[4];
    vorig[0] = zv.x - lr * (g0 - gamma * yv.x);
    vorig[1] = zv.y - lr * (g1 - gamma * yv.y);
    vorig[2] = zv.z - lr * (g2 - gamma * yv.z);
    vorig[3] = zv.w - lr * (g3 - gamma * yv.w);
#pragma unroll
    for (int r = 0; r < 4; r++) val[r] = vorig[r];

    cswap(val[0], val[1], true);
    cswap(val[2], val[3], false);
    {
        const bool a = (lane & 1) == 0;
        cswap(val[0], val[2], a); cswap(val[1], val[3], a);
        cswap(val[0], val[1], a); cswap(val[2], val[3], a);
    }

#define SHFL_LEVEL(ls, asc) do {                                         \
        const bool _low = (lane & (ls)) == 0;                            \
        _Pragma("unroll")                                                \
        for (int r = 0; r < 4; r++) {                                    \
            const float pv = __shfl_xor_sync(FULL, val[r], (ls));        \
            val[r] = (_low == (asc)) ? fminf(val[r], pv)                 \
                                     : fmaxf(val[r], pv);                \
        }                                                                \
    } while (0)

#define REG_TAIL(asc) do {                                               \
        cswap(val[0], val[2], (asc)); cswap(val[1], val[3], (asc));      \
        cswap(val[0], val[1], (asc)); cswap(val[2], val[3], (asc));      \
    } while (0)

    { const bool a = (lane & 2)  == 0; SHFL_LEVEL(1, a); REG_TAIL(a); }
    { const bool a = (lane & 4)  == 0; SHFL_LEVEL(2, a); SHFL_LEVEL(1, a); REG_TAIL(a); }
    { const bool a = (lane & 8)  == 0; SHFL_LEVEL(4, a); SHFL_LEVEL(2, a); SHFL_LEVEL(1, a); REG_TAIL(a);}
    { const bool a = (lane & 16) == 0; SHFL_LEVEL(8, a); SHFL_LEVEL(4, a); SHFL_LEVEL(2, a);
      SHFL_LEVEL(1, a); REG_TAIL(a); }
    { SHFL_LEVEL(16, true); SHFL_LEVEL(8, true); SHFL_LEVEL(4, true); SHFL_LEVEL(2, true);
      SHFL_LEVEL(1, true); REG_TAIL(true); }

#undef SHFL_LEVEL
#undef REG_TAIL

    const float s0 = val[0];
    const float s1 = s0 + val[1];
    const float s2 = s1 + val[2];
    const float s3 = s2 + val[3];
    float incl = s3;
#pragma unroll
    for (int d = 1; d < 32; d <<= 1) {
        const float y = __shfl_up_sync(FULL, incl, d);
        if (lane >= d) incl += y;
    }
    const float prefix = incl - s3;
    const float Stot = __shfl_sync(FULL, incl, 31);
    const float P[4] = { s0 + prefix, s1 + prefix, s2 + prefix, s3 + prefix };

    int rho = 0;
    float cssr[4];
#pragma unroll
    for (int r = 0; r < 4; r++) {
        const int i = lane * 4 + r;
        const float css = Stot - P[r] + val[r];
        cssr[r] = css;
        const bool cond = (val[r] + (1.0f - css) / (float)(128 - i)) > 0.0f;
        rho += __popc(__ballot_sync(FULL, cond));
    }

    const int it = 128 - rho;
    const int Lt = it >> 2, rt = it & 3;
    const float sel = (rt == 0) ? cssr[0] : (rt == 1) ? cssr[1]
                    : (rt == 2) ? cssr[2] : cssr[3];
    const float css_t = __shfl_sync(FULL, sel, Lt);
    const float theta = (css_t - 1.0f) / (float)rho;

    float4 zo;
    zo.x = fmaxf(vorig[0] - theta, 0.0f);
    zo.y = fmaxf(vorig[1] - theta, 0.0f);
    zo.z = fmaxf(vorig[2] - theta, 0.0f);
    zo.w = fmaxf(vorig[3] - theta, 0.0f);
    *reinterpret_cast<float4*>(&zz[lane * 4]) = zo;
}

// ---------------------------------------------------------------------------
// Kernel 2: 512 threads (16 warps), one CTA per TWO scenarios. Each warp owns
// 16 matrix rows in registers (epB: 32 u64 = 64 regs). Per-thread FMA work
// halves vs the 256-thread version while the instruction STRUCTURE is
// conserved, doubling warps/SMSP to hide latency. Butterfly: fused d=8 level,
// then d=4,2,1, then one bit-16 fold = 16 shfls; lane L holds r for row
// 16*wid + (L & 15), duplicated across half-warps (deterministic identical).
// ---------------------------------------------------------------------------
__global__ __launch_bounds__(NTHREADS, 1)
void solver_kernel(const float* __restrict__ yhat_all,
                   const float* __restrict__ delta_p,
                   const float* __restrict__ gamma_p,
                   float* __restrict__ zout) {
    __shared__ float zA[N_Y], zB[N_Y];
    __shared__ float yhA[N_Y], yhB[N_Y];
    __shared__ u64 wAs[N_OBS], wBs[N_OBS];     // splatted (w,w) pairs
    __shared__ float partA[NWARPS * N_Y], partB[NWARPS * N_Y];
    __shared__ float redIA[NWARPS], redWA[NWARPS], redIB[NWARPS], redWB[NWARPS];
    __shared__ float cAs, etaAs, lamAs, cBs, etaBs, lamBs;

    const int tid  = threadIdx.x;
    const int lane = tid & 31;
    const int wid  = tid >> 5;
    const int sA = blockIdx.x * 2;
    const int sB = sA + 1;
    const float delta = *delta_p;
    const float gamma = *gamma_p;
    const unsigned FULL = 0xffffffffu;

    if (tid < N_Y) {
        zA[tid] = 1.0f / (float)N_Y;
        zB[tid] = 1.0f / (float)N_Y;
        yhA[tid] = yhat_all[sA * N_Y + tid];
        yhB[tid] = yhat_all[sB * N_Y + tid];
    }
    if (tid == 0) { cAs = 0.0f; etaAs = 0.0f; lamAs = 0.1f;
                    cBs = 0.0f; etaBs = 0.0f; lamBs = 0.1f; }

    // Register matrix cache: warp owns rows 16*wid .. 16*wid+15;
    // lane holds columns 4*lane..4*lane+3 of each row (2 u64 per row).
    u64 epB[2 * ROWS_PER_WARP];
#pragma unroll
    for (int tt = 0; tt < ROWS_PER_WARP; tt++) {
        const float4 e = *reinterpret_cast<const float4*>(
            &g_ep[(ROWS_PER_WARP * wid + tt) * N_Y + 4 * lane]);
        epB[2 * tt]     = pk2(e.x, e.y);
        epB[2 * tt + 1] = pk2(e.z, e.w);
    }
    __syncthreads();

    for (int k = 0; k < NITERS; k++) {
        const float lr = 0.05f / sqrtf(1.0f + (float)k);
        const float cA = cAs, etaA = etaAs, lamA = lamAs;
        const float cB = cBs, etaB = etaBs, lamB = lamBs;

        // ---- Phase A: packed partial dots + 16-row butterfly ----
        const float4 zva = *reinterpret_cast<const float4*>(&zA[4 * lane]);
        const float4 zvb = *reinterpret_cast<const float4*>(&zB[4 * lane]);
        const u64 zA0 = pk2(zva.x, zva.y), zA1 = pk2(zva.z, zva.w);
        const u64 zB0 = pk2(zvb.x, zvb.y), zB1 = pk2(zvb.z, zvb.w);

        const bool hi8 = (lane & 8) != 0;
        u64 q[8];   // packed (partialA, partialB); d=8 level folded in
#pragma unroll
        for (int i = 0; i < 8; i++) {
            u64 a = 0, b = 0;
            fma2(a, epB[2 * i],         zA0);
            fma2(a, epB[2 * i + 1],     zA1);
            fma2(b, epB[2 * i],         zB0);
            fma2(b, epB[2 * i + 1],     zB1);
            const u64 pi = pk2(upk_sum(a), upk_sum(b));

            u64 a2 = 0, b2 = 0;
            fma2(a2, epB[2 * (i + 8)],     zA0);
            fma2(a2, epB[2 * (i + 8) + 1], zA1);
            fma2(b2, epB[2 * (i + 8)],     zB0);
            fma2(b2, epB[2 * (i + 8) + 1], zB1);
            const u64 pj = pk2(upk_sum(a2), upk_sum(b2));

            u64 keep = hi8 ? pj : pi;
            const u64 send = hi8 ? pi : pj;
            add2(keep, __shfl_xor_sync(FULL, send, 8));
            q[i] = keep;
        }

        // remaining butterfly levels d = 4,2,1 on q[0..7]
#pragma unroll
        for (int d = 4; d >= 1; d >>= 1) {
            const bool hi = (lane & d) != 0;
#pragma unroll
            for (int i = 0; i < d; i++) {
                u64 keep = hi ? q[i + d] : q[i];
                const u64 send = hi ? q[i] : q[i + d];
                add2(keep, __shfl_xor_sync(FULL, send, d));
                q[i] = keep;
            }
        }
        // fold remaining lane bit 16 (rows duplicated across half-warps)
        add2(q[0], __shfl_xor_sync(FULL, q[0], 16));

        const float rA = upk_lo(q[0]) - cA;   // r for t = 16*wid + (lane & 15)
        const float rB = upk_hi(q[0]) - cB;

        const float aAv = rA * rA - etaA;
        const float aBv = rB * rB - etaB;
        const float IA = (aAv > -lamA) ? 1.0f : ((aAv < -lamA) ? 0.0f : 0.5f);
        const float IB = (aBv > -lamB) ? 1.0f : ((aBv < -lamB) ? 0.0f : 0.5f);
        const float wAv = IA * 2.0f * rA * (1.0f / (float)N_OBS);
        const float wBv = IB * 2.0f * rB * (1.0f / (float)N_OBS);

        // Splat (w,w) pairs for Phase B (rows duplicated: lanes 0-15 write).
        if (lane < ROWS_PER_WARP) {
            wAs[ROWS_PER_WARP * wid + lane] = pk2(wAv, wAv);
            wBs[ROWS_PER_WARP * wid + lane] = pk2(wBv, wBv);
        }

        // Per-warp scalar reductions (values duplicated 2x -> scale 0.5)
        {
            u64 sI = pk2(IA, IB);
            u64 sW = pk2(wAv, wBv);
#pragma unroll
            for (int d = 16; d >= 1; d >>= 1) {
                add2(sI, __shfl_xor_sync(FULL, sI, d));
                add2(sW, __shfl_xor_sync(FULL, sW, d));
            }
            if (lane == 0) {
                redIA[wid] = 0.5f * upk_lo(sI); redIB[wid] = 0.5f * upk_hi(sI);
                redWA[wid] = 0.5f * upk_lo(sW); redWB[wid] = 0.5f * upk_hi(sW);
            }
        }
        __syncwarp();   // own-warp wAs/wBs visible

        // ---- Phase B: per-warp partial g_z over own 16 rows ----
        {
            const u64* wa = &wAs[ROWS_PER_WARP * wid];
            const u64* wb = &wBs[ROWS_PER_WARP * wid];
            u64 gA0 = 0, gA1 = 0, gB0 = 0, gB1 = 0;
#pragma unroll
            for (int tt = 0; tt < ROWS_PER_WARP; tt++) {
                const u64 wap = wa[tt];   // LDS.64 broadcast
                const u64 wbp = wb[tt];
                fma2(gA0, epB[2 * tt],     wap);
                fma2(gA1, epB[2 * tt + 1], wap);
                fma2(gB0, epB[2 * tt],     wbp);
                fma2(gB1, epB[2 * tt + 1], wbp);
            }
            float4 oa, ob;
            oa.x = upk_lo(gA0); oa.y = upk_hi(gA0);
            oa.z = upk_lo(gA1); oa.w = upk_hi(gA1);
            ob.x = upk_lo(gB0); ob.y = upk_hi(gB0);
            ob.z = upk_lo(gB1); ob.w = upk_hi(gB1);
            *reinterpret_cast<float4*>(&partA[wid * N_Y + 4 * lane]) = oa;
            *reinterpret_cast<float4*>(&partB[wid * N_Y + 4 * lane]) = ob;
        }
        __syncthreads();   // B2: partials + reductions visible

        // ---- window: projections (warps 0,1) + scalar updates (warp 2) ----
        if (wid == 0) {
            project_warp16(partA, yhA, zA, lr, gamma);
        } else if (wid == 1) {
            project_warp16(partB, yhB, zB, lr, gamma);
        } else if (wid == 2) {
            if (lane == 0) {
                float SI = 0.0f, SW = 0.0f;
#pragma unroll
                for (int i = 0; i < NWARPS; i++) { SI += redIA[i]; SW += redWA[i]; }
                cAs   = cA + lr * SW;
                etaAs = etaA - lr * (1.0f - SI * (1.0f / (float)N_OBS));
                lamAs = fmaxf(lamA - lr * (delta - 1.0f + SI * (1.0f / (float)N_OBS)), 0.0f);
            } else if (lane == 1) {
                float SI = 0.0f, SW = 0.0f;
#pragma unroll
                for (int i = 0; i < NWARPS; i++) { SI += redIB[i]; SW += redWB[i]; }
                cBs   = cB + lr * SW;
                etaBs = etaB - lr * (1.0f - SI * (1.0f / (float)N_OBS));
                lamBs = fmaxf(lamB - lr * (delta - 1.0f + SI * (1.0f / (float)N_OBS)), 0.0f);
            }
        }
        __syncthreads();   // B3: new z + scalars visible
    }

    if (tid < 128) {
        zout[sA * N_Y + tid] = zA[tid];
    } else if (tid < 256) {
        zout[sB * N_Y + (tid - 128)] = zB[tid - 128];
    }
}

// ---------------------------------------------------------------------------
extern "C" void kernel_launch(void* const* d_in, const int* in_sizes, int n_in,
                              void* d_out, int out_size) {
    const float* X     = (const float*)d_in[0];
    const float* Y     = (const float*)d_in[1];
    const float* W     = (const float*)d_in[2];
    const float* b     = (const float*)d_in[3];
    const float* delta = (const float*)d_in[4];
    const float* gamma = (const float*)d_in[5];

    float* out = (float*)d_out;
    float* zout = out;
    float* yhat;
    if (out_size >= 2 * N_OBS * N_Y) {
        yhat = out + N_OBS * N_Y;
    } else {
        void* p = nullptr;
        cudaGetSymbolAddress(&p, g_yhat_fallback);
        yhat = (float*)p;
    }

    prep_kernel<<<N_OBS, N_Y>>>(X, Y, W, b, yhat);
    solver_kernel<<<N_OBS / 2, NTHREADS>>>(yhat, delta, gamma, zout);
}

// round 14
// speedup vs baseline: 1.1978x; 1.1978x over previous
#include <cuda_runtime.h>
#include <math.h>

#define N_OBS   256
#define N_Y     128
#define N_X     64
#define NITERS  150
#define NTHREADS 320          // 8 matrix warps + 2 projector warps
#define MWARPS   8
#define BARCNT   288          // 256 matrix threads + 32 projector threads

__device__ float g_ep[N_OBS * N_Y];             // ep row-major [t][j]
__device__ float g_yhat_fallback[N_OBS * N_Y];

// ---- packed f32x2 helpers (sm_103a) ---------------------------------------
typedef unsigned long long u64;
__device__ __forceinline__ void fma2(u64& d, u64 a, u64 b) {
    asm("fma.rn.f32x2 %0, %1, %2, %0;" : "+l"(d) : "l"(a), "l"(b));
}
__device__ __forceinline__ void add2(u64& d, u64 a) {
    asm("add.rn.f32x2 %0, %0, %1;" : "+l"(d) : "l"(a));
}
__device__ __forceinline__ u64 pk2(float lo, float hi) {
    u64 r;
    asm("mov.b64 %0, {%1, %2};" : "=l"(r) : "f"(lo), "f"(hi));
    return r;
}
__device__ __forceinline__ float upk_lo(u64 v) {
    float lo, hi; asm("mov.b64 {%0, %1}, %2;" : "=f"(lo), "=f"(hi) : "l"(v)); return lo;
}
__device__ __forceinline__ float upk_hi(u64 v) {
    float lo, hi; asm("mov.b64 {%0, %1}, %2;" : "=f"(lo), "=f"(hi) : "l"(v)); return hi;
}
__device__ __forceinline__ float upk_sum(u64 v) {
    float lo, hi; asm("mov.b64 {%0, %1}, %2;" : "=f"(lo), "=f"(hi) : "l"(v)); return lo + hi;
}

// ---- named barriers --------------------------------------------------------
#define NBAR_SYNC(id)   asm volatile("bar.sync %0, %1;"   :: "r"(id), "r"(BARCNT) : "memory")
#define NBAR_ARRIVE(id) asm volatile("bar.arrive %0, %1;" :: "r"(id), "r"(BARCNT) : "memory")

// ---------------------------------------------------------------------------
// Kernel 1: Y_hat = X @ W^T + b ; ep = Y - Y_hat (row-major)
// ---------------------------------------------------------------------------
__global__ void prep_kernel(const float* __restrict__ X,
                            const float* __restrict__ Y,
                            const float* __restrict__ W,
                            const float* __restrict__ b,
                            float* __restrict__ yhat_out) {
    __shared__ float Xs[N_X];
    __shared__ float Ws[N_Y * (N_X + 1)];
    const int t = blockIdx.x;
    const int i = threadIdx.x;

    if (i < N_X) Xs[i] = X[t * N_X + i];
    for (int idx = i; idx < N_Y * N_X; idx += blockDim.x) {
        int r = idx >> 6, cx = idx & 63;
        Ws[r * (N_X + 1) + cx] = W[idx];
    }
    __syncthreads();

    float acc = b[i];
#pragma unroll
    for (int x = 0; x < N_X; x++) acc += Xs[x] * Ws[i * (N_X + 1) + x];

    yhat_out[t * N_Y + i] = acc;
    g_ep[t * N_Y + i] = Y[t * N_Y + i] - acc;
}

// ---------------------------------------------------------------------------
// Block-layout warp-local simplex projection: sums 8 per-warp partials,
// v = z - lr*(g - gamma*yh), z = proj_simplex(v). i = lane*4 + r.
// ---------------------------------------------------------------------------
__device__ __forceinline__ void cswap(float& a, float& b, bool asc) {
    const float lo = fminf(a, b), hi = fmaxf(a, b);
    a = asc ? lo : hi;
    b = asc ? hi : lo;
}

__device__ __forceinline__ void project_warp8(const float* __restrict__ part,
                                              const float* __restrict__ yh,
                                              float* __restrict__ zz,
                                              float lr, float gamma) {
    const unsigned FULL = 0xffffffffu;
    const int lane = threadIdx.x & 31;

    float g0 = 0.0f, g1 = 0.0f, g2 = 0.0f, g3 = 0.0f;
#pragma unroll
    for (int w = 0; w < MWARPS; w++) {
        const float4 p = *reinterpret_cast<const float4*>(&part[w * N_Y + lane * 4]);
        g0 += p.x; g1 += p.y; g2 += p.z; g3 += p.w;
    }
    const float4 yv = *reinterpret_cast<const float4*>(&yh[lane * 4]);
    const float4 zv = *reinterpret_cast<const float4*>(&zz[lane * 4]);

    float vorig[4], val[4];
    vorig[0] = zv.x - lr * (g0 - gamma * yv.x);
    vorig[1] = zv.y - lr * (g1 - gamma * yv.y);
    vorig[2] = zv.z - lr * (g2 - gamma * yv.z);
    vorig[3] = zv.w - lr * (g3 - gamma * yv.w);
#pragma unroll
    for (int r = 0; r < 4; r++) val[r] = vorig[r];

    cswap(val[0], val[1], true);
    cswap(val[2], val[3], false);
    {
        const bool a = (lane & 1) == 0;
        cswap(val[0], val[2], a); cswap(val[1], val[3], a);
        cswap(val[0], val[1], a); cswap(val[2], val[3], a);
    }

#define SHFL_LEVEL(ls, asc) do {                                         \
        const bool _low = (lane & (ls)) == 0;                            \
        _Pragma("unroll")                                                \
        for (int r = 0; r < 4; r++) {                                    \
            const float pv = __shfl_xor_sync(FULL, val[r], (ls));        \
            val[r] = (_low == (asc)) ? fminf(val[r], pv)                 \
                                     : fmaxf(val[r], pv);                \
        }                                                                \
    } while (0)

#define REG_TAIL(asc) do {                                               \
        cswap(val[0], val[2], (asc)); cswap(val[1], val[3], (asc));      \
        cswap(val[0], val[1], (asc)); cswap(val[2], val[3], (asc));      \
    } while (0)

    { const bool a = (lane & 2)  == 0; SHFL_LEVEL(1, a); REG_TAIL(a); }
    { const bool a = (lane & 4)  == 0; SHFL_LEVEL(2, a); SHFL_LEVEL(1, a); REG_TAIL(a); }
    { const bool a = (lane & 8)  == 0; SHFL_LEVEL(4, a); SHFL_LEVEL(2, a); SHFL_LEVEL(1, a); REG_TAIL(a);}
    { const bool a = (lane & 16) == 0; SHFL_LEVEL(8, a); SHFL_LEVEL(4, a); SHFL_LEVEL(2, a);
      SHFL_LEVEL(1, a); REG_TAIL(a); }
    { SHFL_LEVEL(16, true); SHFL_LEVEL(8, true); SHFL_LEVEL(4, true); SHFL_LEVEL(2, true);
      SHFL_LEVEL(1, true); REG_TAIL(true); }

#undef SHFL_LEVEL
#undef REG_TAIL

    const float s0 = val[0];
    const float s1 = s0 + val[1];
    const float s2 = s1 + val[2];
    const float s3 = s2 + val[3];
    float incl = s3;
#pragma unroll
    for (int d = 1; d < 32; d <<= 1) {
        const float y = __shfl_up_sync(FULL, incl, d);
        if (lane >= d) incl += y;
    }
    const float prefix = incl - s3;
    const float Stot = __shfl_sync(FULL, incl, 31);
    const float P[4] = { s0 + prefix, s1 + prefix, s2 + prefix, s3 + prefix };

    int rho = 0;
    float cssr[4];
#pragma unroll
    for (int r = 0; r < 4; r++) {
        const int i = lane * 4 + r;
        const float css = Stot - P[r] + val[r];
        cssr[r] = css;
        const bool cond = (val[r] + (1.0f - css) / (float)(128 - i)) > 0.0f;
        rho += __popc(__ballot_sync(FULL, cond));
    }

    const int it = 128 - rho;
    const int Lt = it >> 2, rt = it & 3;
    const float sel = (rt == 0) ? cssr[0] : (rt == 1) ? cssr[1]
                    : (rt == 2) ? cssr[2] : cssr[3];
    const float css_t = __shfl_sync(FULL, sel, Lt);
    const float theta = (css_t - 1.0f) / (float)rho;

    float4 zo;
    zo.x = fmaxf(vorig[0] - theta, 0.0f);
    zo.y = fmaxf(vorig[1] - theta, 0.0f);
    zo.z = fmaxf(vorig[2] - theta, 0.0f);
    zo.w = fmaxf(vorig[3] - theta, 0.0f);
    *reinterpret_cast<float4*>(&zz[lane * 4]) = zo;
}

// ---------------------------------------------------------------------------
// Matrix-warp work for ONE scenario: sync(z-ready), dot+butterfly -> r_t,
// indicator/w, red sums, g_z partial, arrive(data-ready).
// Butterfly fuses bit-16 and bit-8 levels into the dot loop (q[8] live).
// Lane L ends holding r for row 32*wid + L.
// ---------------------------------------------------------------------------
template<int ZBAR, int DBAR>
__device__ __forceinline__ void mat_scenario(const u64* epB,
                                             const float* __restrict__ zz,
                                             const float* __restrict__ sc,
                                             float* __restrict__ redI,
                                             float* __restrict__ redW,
                                             float* __restrict__ part,
                                             int lane, int wid) {
    const unsigned FULL = 0xffffffffu;
    NBAR_SYNC(ZBAR);
    const float c = sc[0], eta = sc[1], lam = sc[2];
    const float4 zv = *reinterpret_cast<const float4*>(&zz[4 * lane]);
    const u64 z0 = pk2(zv.x, zv.y), z1 = pk2(zv.z, zv.w);

    const bool hi16 = (lane & 16) != 0;
    const bool hi8  = (lane & 8) != 0;
    float q[8];
#pragma unroll
    for (int i = 0; i < 8; i++) {
        u64 a0 = 0, a1 = 0, a2 = 0, a3 = 0;
        fma2(a0, epB[2 * i],            z0); fma2(a0, epB[2 * i + 1],            z1);
        fma2(a1, epB[2 * (i + 8)],      z0); fma2(a1, epB[2 * (i + 8) + 1],      z1);
        fma2(a2, epB[2 * (i + 16)],     z0); fma2(a2, epB[2 * (i + 16) + 1],     z1);
        fma2(a3, epB[2 * (i + 24)],     z0); fma2(a3, epB[2 * (i + 24) + 1],     z1);
        const float p0  = upk_sum(a0);
        const float p8  = upk_sum(a1);
        const float p16 = upk_sum(a2);
        const float p24 = upk_sum(a3);
        // fold lane bit 16: pairs (p0,p16), (p8,p24)
        float ka = hi16 ? p16 : p0;
        const float sa = hi16 ? p0 : p16;
        ka += __shfl_xor_sync(FULL, sa, 16);
        float kb = hi16 ? p24 : p8;
        const float sb = hi16 ? p8 : p24;
        kb += __shfl_xor_sync(FULL, sb, 16);
        // fold lane bit 8: pair (ka, kb)
        const float kc = hi8 ? kb : ka;
        const float sc2 = hi8 ? ka : kb;
        q[i] = kc + __shfl_xor_sync(FULL, sc2, 8);
    }
#pragma unroll
    for (int d = 4; d >= 1; d >>= 1) {
        const bool hi = (lane & d) != 0;
#pragma unroll
        for (int i = 0; i < d; i++) {
            const float keep = hi ? q[i + d] : q[i];
            const float send = hi ? q[i] : q[i + d];
            q[i] = keep + __shfl_xor_sync(FULL, send, d);
        }
    }
    const float r = q[0] - c;             // row 32*wid + lane
    const float av = r * r - eta;
    const float I = (av > -lam) ? 1.0f : ((av < -lam) ? 0.0f : 0.5f);
    const float w = I * 2.0f * r * (1.0f / (float)N_OBS);

    // red sums (I, w) packed butterfly
    u64 s = pk2(I, w);
#pragma unroll
    for (int d = 16; d >= 1; d >>= 1) add2(s, __shfl_xor_sync(FULL, s, d));
    if (lane == 0) { redI[wid] = upk_lo(s); redW[wid] = upk_hi(s); }

    // g_z partial over own 32 rows (w via f32 shfl)
    u64 g0 = 0, g1 = 0;
#pragma unroll
    for (int tt = 0; tt < 32; tt++) {
        const float wt = __shfl_sync(FULL, w, tt);
        const u64 wp = pk2(wt, wt);
        fma2(g0, epB[2 * tt],     wp);
        fma2(g1, epB[2 * tt + 1], wp);
    }
    float4 o;
    o.x = upk_lo(g0); o.y = upk_hi(g0); o.z = upk_lo(g1); o.w = upk_hi(g1);
    *reinterpret_cast<float4*>(&part[wid * N_Y + 4 * lane]) = o;
    NBAR_ARRIVE(DBAR);
}

// ---------------------------------------------------------------------------
// Kernel 2: 320 threads: 8 matrix warps (register matrix, R10 structure) +
// projector warp 8 (scenario A) + projector warp 9 (scenario B).
// Named-barrier pipeline: A's projection overlaps matrix warps' B stretch.
//   matrix:  sync(ZA) A-work arrive(DA) sync(ZB) B-work arrive(DB) ...
//   proj A:  arrive(ZA) sync(DA) scalars+project(write zA,scA) ...
// ---------------------------------------------------------------------------
__global__ __launch_bounds__(NTHREADS, 1)
void solver_kernel(const float* __restrict__ yhat_all,
                   const float* __restrict__ delta_p,
                   const float* __restrict__ gamma_p,
                   float* __restrict__ zout) {
    __shared__ float zA[N_Y], zB[N_Y];
    __shared__ float yhA[N_Y], yhB[N_Y];
    __shared__ float partA[MWARPS * N_Y], partB[MWARPS * N_Y];
    __shared__ float redIA[MWARPS], redWA[MWARPS], redIB[MWARPS], redWB[MWARPS];
    __shared__ float scA[3], scB[3];   // c, eta, lam

    const int tid  = threadIdx.x;
    const int lane = tid & 31;
    const int wid  = tid >> 5;
    const int sA = blockIdx.x * 2;
    const int sB = sA + 1;
    const float delta = *delta_p;
    const float gamma = *gamma_p;

    if (tid < N_Y) {
        zA[tid] = 1.0f / (float)N_Y;
        zB[tid] = 1.0f / (float)N_Y;
        yhA[tid] = yhat_all[sA * N_Y + tid];
        yhB[tid] = yhat_all[sB * N_Y + tid];
    }
    if (tid == 0) { scA[0] = 0.0f; scA[1] = 0.0f; scA[2] = 0.1f;
                    scB[0] = 0.0f; scB[1] = 0.0f; scB[2] = 0.1f; }

    u64 epB[64];
    if (wid < MWARPS) {
#pragma unroll
        for (int tt = 0; tt < 32; tt++) {
            const float4 e = *reinterpret_cast<const float4*>(
                &g_ep[(32 * wid + tt) * N_Y + 4 * lane]);
            epB[2 * tt]     = pk2(e.x, e.y);
            epB[2 * tt + 1] = pk2(e.z, e.w);
        }
    }
    __syncthreads();

    if (wid < MWARPS) {
        // ---- matrix warps ----
        for (int k = 0; k < NITERS; k++) {
            mat_scenario<1, 2>(epB, zA, scA, redIA, redWA, partA, lane, wid);
            mat_scenario<3, 4>(epB, zB, scB, redIB, redWB, partB, lane, wid);
        }
    } else if (wid == MWARPS) {
        // ---- projector warp for scenario A (owns cA/etaA/lamA in regs) ----
        float c = 0.0f, eta = 0.0f, lam = 0.1f;
        for (int k = 0; k < NITERS; k++) {
            const float lr = 0.05f / sqrtf(1.0f + (float)k);
            NBAR_ARRIVE(1);        // publish zA_k + scalars_k
            NBAR_SYNC(2);          // wait matrix data
            float SI = 0.0f, SW = 0.0f;
#pragma unroll
            for (int i = 0; i < MWARPS; i++) { SI += redIA[i]; SW += redWA[i]; }
            c   += lr * SW;
            eta -= lr * (1.0f - SI * (1.0f / (float)N_OBS));
            lam  = fmaxf(lam - lr * (delta - 1.0f + SI * (1.0f / (float)N_OBS)), 0.0f);
            if (lane == 0) { scA[0] = c; scA[1] = eta; scA[2] = lam; }
            project_warp8(partA, yhA, zA, lr, gamma);
        }
    } else {
        // ---- projector warp for scenario B ----
        float c = 0.0f, eta = 0.0f, lam = 0.1f;
        for (int k = 0; k < NITERS; k++) {
            const float lr = 0.05f / sqrtf(1.0f + (float)k);
            NBAR_ARRIVE(3);
            NBAR_SYNC(4);
            float SI = 0.0f, SW = 0.0f;
#pragma unroll
            for (int i = 0; i < MWARPS; i++) { SI += redIB[i]; SW += redWB[i]; }
            c   += lr * SW;
            eta -= lr * (1.0f - SI * (1.0f / (float)N_OBS));
            lam  = fmaxf(lam - lr * (delta - 1.0f + SI * (1.0f / (float)N_OBS)), 0.0f);
            if (lane == 0) { scB[0] = c; scB[1] = eta; scB[2] = lam; }
            project_warp8(partB, yhB, zB, lr, gamma);
        }
    }
    __syncthreads();

    if (tid < 128) {
        zout[sA * N_Y + tid] = zA[tid];
    } else if (tid < 256) {
        zout[sB * N_Y + (tid - 128)] = zB[tid - 128];
    }
}

// ---------------------------------------------------------------------------
extern "C" void kernel_launch(void* const* d_in, const int* in_sizes, int n_in,
                              void* d_out, int out_size) {
    const float* X     = (const float*)d_in[0];
    const float* Y     = (const float*)d_in[1];
    const float* W     = (const float*)d_in[2];
    const float* b     = (const float*)d_in[3];
    const float* delta = (const float*)d_in[4];
    const float* gamma = (const float*)d_in[5];

    float* out = (float*)d_out;
    float* zout = out;
    float* yhat;
    if (out_size >= 2 * N_OBS * N_Y) {
        yhat = out + N_OBS * N_Y;
    } else {
        void* p = nullptr;
        cudaGetSymbolAddress(&p, g_yhat_fallback);
        yhat = (float*)p;
    }

    prep_kernel<<<N_OBS, N_Y>>>(X, Y, W, b, yhat);
    solver_kernel<<<N_OBS / 2, NTHREADS>>>(yhat, delta, gamma, zout);
}